// round 10
// baseline (speedup 1.0000x reference)
#include <cuda_runtime.h>
#include <cstdint>

// Problem constants
#define Bc 16
#define Sc 24
#define Lc 128
#define Dc 768
#define Ac 8
#define Tc 8
#define NSLOT 24          // 3 arg types * A=8
#define NST (NSLOT * Tc)  // 192
#define MAXPAIRS (NSLOT * Lc)   // 3072 worst case

#define NTHR 64           // threads per CTA
#define RPB 7             // blocks per bs: 6 meanpool (3 colsplit x 2 Lsplit) + 1 slot

// ---------------- Kernel 0: zero the mean-pool output region ----------------
__global__ __launch_bounds__(256)
void srl_zero_kernel(float* __restrict__ out)
{
    // Bc*Sc*Dc = 294912 floats = 73728 float4
    int i = blockIdx.x * 256 + threadIdx.x;
    ((float4*)out)[i] = make_float4(0.f, 0.f, 0.f, 0.f);
}

// ---------------- Main kernel: meanpool (L-split, atomic) + slot gather -----
__global__ __launch_bounds__(NTHR, 20)
void srl_main_kernel(const float* __restrict__ emb,
                     const int* __restrict__ masks,
                     const int* __restrict__ sids,
                     const int* __restrict__ pred_ids,
                     const int* __restrict__ arg0_ids,
                     const int* __restrict__ arg1_ids,
                     float* __restrict__ out)
{
    __shared__ float          s_maskf[Lc];
    __shared__ float          s_wcnt[2];
    __shared__ int            s_sid[Lc];
    __shared__ int            s_argids[NST];
    __shared__ int            s_cnt[NST];
    __shared__ int            s_chosen[NSLOT];
    __shared__ float          s_invc[NSLOT];
    __shared__ int            s_nm[NSLOT];
    __shared__ int            s_off[NSLOT + 1];
    __shared__ unsigned short s_pairs[MAXPAIRS];  // (slot<<8)|l, slot-major

    const int blk = blockIdx.x;
    const int bs  = blk / RPB;
    const int r   = blk % RPB;
    const int tid = threadIdx.x;

    const size_t OFF0 = (size_t)Bc * Sc * Dc;
    const size_t ASZ  = (size_t)Bc * Sc * Ac * Dc;

    if (r < 6) {
        // ================= mean-pool block: 256 cols, 64 rows ================
        const int cy = r % 3;       // column split
        const int lh = r / 3;       // L half

        // stage full mask, compute total count
        float m0 = (float)masks[bs * Lc + tid];
        float m1 = (float)masks[bs * Lc + tid + 64];
        s_maskf[tid]      = m0;
        s_maskf[tid + 64] = m1;
        {
            float c = m0 + m1;
            #pragma unroll
            for (int off = 16; off; off >>= 1)
                c += __shfl_xor_sync(0xffffffffu, c, off);
            if ((tid & 31) == 0) s_wcnt[tid >> 5] = c;
        }
        __syncthreads();
        const float inv = 1.0f / fmaxf(s_wcnt[0] + s_wcnt[1], 1.0f);

        const int colv = cy * 64 + tid;   // float4 column index (0..191)
        const float4* ep = (const float4*)(emb + (size_t)bs * Lc * Dc) + colv;
        const int lbase = lh * 64;

        float4 acc = make_float4(0.f, 0.f, 0.f, 0.f);

        #pragma unroll 1
        for (int lb = 0; lb < 64; lb += 8) {
            float4 v[8];
            #pragma unroll
            for (int i = 0; i < 8; i++)
                v[i] = ep[(size_t)(lbase + lb + i) * (Dc / 4)];
            #pragma unroll
            for (int i = 0; i < 8; i++) {
                float mf = s_maskf[lbase + lb + i];
                acc.x = fmaf(v[i].x, mf, acc.x);
                acc.y = fmaf(v[i].y, mf, acc.y);
                acc.z = fmaf(v[i].z, mf, acc.z);
                acc.w = fmaf(v[i].w, mf, acc.w);
            }
        }

        // exactly two commutative adds per element -> deterministic
        float* o = out + (size_t)bs * Dc + colv * 4;
        atomicAdd(o + 0, acc.x * inv);
        atomicAdd(o + 1, acc.y * inv);
        atomicAdd(o + 2, acc.z * inv);
        atomicAdd(o + 3, acc.w * inv);
        return;
    }

    // ==================== slot-gather block (r == 6) =========================
    // stage metadata
    s_sid[tid]      = sids[bs * Lc + tid];
    s_sid[tid + 64] = sids[bs * Lc + tid + 64];
    #pragma unroll
    for (int i = tid; i < NST; i += NTHR) {
        int slot = i / Tc, t = i % Tc;
        int type = slot / Ac, a = slot % Ac;
        const int* src = (type == 0) ? pred_ids : (type == 1) ? arg0_ids : arg1_ids;
        s_argids[i] = src[(bs * Ac + a) * Tc + t];
    }
    __syncthreads();

    // per-(slot,t) match counts
    #pragma unroll
    for (int i = tid; i < NST; i += NTHR) {
        int id = s_argids[i];
        int c = 0;
        if (id != 0) {
            #pragma unroll 8
            for (int l = 0; l < Lc; l++) c += (s_sid[l] == id);
        }
        s_cnt[i] = c;
    }
    __syncthreads();

    // per-slot chosen id / count
    if (tid < NSLOT) {
        int chosen = -1, nm = 0;
        float invc = 1.0f;
        #pragma unroll
        for (int t = Tc - 1; t >= 0; t--) {
            int c = s_cnt[tid * Tc + t];
            if (c > 0) { chosen = s_argids[tid * Tc + t]; nm = c;
                         invc = 1.0f / (float)c; break; }
        }
        s_chosen[tid] = chosen;
        s_invc[tid]   = invc;
        s_nm[tid]     = nm;
    }
    __syncthreads();

    if (tid == 0) {
        int o = 0;
        #pragma unroll
        for (int s = 0; s < NSLOT; s++) { s_off[s] = o; o += s_nm[s]; }
        s_off[NSLOT] = o;
    }
    __syncthreads();

    // build flat pair list (slot-major, l-ordered => deterministic)
    if (tid < NSLOT && s_nm[tid] > 0) {
        int id = s_chosen[tid];
        int o  = s_off[tid];
        #pragma unroll 4
        for (int l = 0; l < Lc; l++)
            if (s_sid[l] == id)
                s_pairs[o++] = (unsigned short)((tid << 8) | l);
    }
    __syncthreads();

    const int npairs = s_off[NSLOT];

    // zero outputs for empty slots (each thread owns 3 float4 columns)
    #pragma unroll
    for (int s = 0; s < NSLOT; s++) {
        if (s_nm[s] == 0) {
            int type = s / Ac, a = s % Ac;
            float4* o = (float4*)(out + OFF0 + (size_t)type * ASZ
                                  + ((size_t)bs * Ac + a) * Dc);
            o[tid]       = make_float4(0.f, 0.f, 0.f, 0.f);
            o[tid + 64]  = make_float4(0.f, 0.f, 0.f, 0.f);
            o[tid + 128] = make_float4(0.f, 0.f, 0.f, 0.f);
        }
    }

    // batched gather: 2 rows x 3 float4 in flight, flush on slot change
    const float4* ebase = (const float4*)(emb + (size_t)bs * Lc * Dc);
    float4 a0v = make_float4(0.f,0.f,0.f,0.f);
    float4 a1v = make_float4(0.f,0.f,0.f,0.f);
    float4 a2v = make_float4(0.f,0.f,0.f,0.f);
    int cur = -1;

    for (int p0 = 0; p0 < npairs; p0 += 2) {
        const int nb = min(2, npairs - p0);
        float4 v[2][3];
        int    sl[2];
        #pragma unroll
        for (int i = 0; i < 2; i++) {
            if (i < nb) {
                int pr = s_pairs[p0 + i];
                sl[i] = pr >> 8;
                const float4* rp = ebase + (size_t)(pr & 255) * (Dc / 4);
                v[i][0] = rp[tid];
                v[i][1] = rp[tid + 64];
                v[i][2] = rp[tid + 128];
            }
        }
        #pragma unroll
        for (int i = 0; i < 2; i++) {
            if (i < nb) {
                if (sl[i] != cur) {
                    if (cur >= 0) {
                        float inv = s_invc[cur];
                        int type = cur / Ac, a = cur % Ac;
                        float4* o = (float4*)(out + OFF0 + (size_t)type * ASZ
                                              + ((size_t)bs * Ac + a) * Dc);
                        o[tid]       = make_float4(a0v.x*inv, a0v.y*inv, a0v.z*inv, a0v.w*inv);
                        o[tid + 64]  = make_float4(a1v.x*inv, a1v.y*inv, a1v.z*inv, a1v.w*inv);
                        o[tid + 128] = make_float4(a2v.x*inv, a2v.y*inv, a2v.z*inv, a2v.w*inv);
                    }
                    cur = sl[i];
                    a0v = v[i][0]; a1v = v[i][1]; a2v = v[i][2];
                } else {
                    a0v.x += v[i][0].x; a0v.y += v[i][0].y; a0v.z += v[i][0].z; a0v.w += v[i][0].w;
                    a1v.x += v[i][1].x; a1v.y += v[i][1].y; a1v.z += v[i][1].z; a1v.w += v[i][1].w;
                    a2v.x += v[i][2].x; a2v.y += v[i][2].y; a2v.z += v[i][2].z; a2v.w += v[i][2].w;
                }
            }
        }
    }
    if (cur >= 0) {
        float inv = s_invc[cur];
        int type = cur / Ac, a = cur % Ac;
        float4* o = (float4*)(out + OFF0 + (size_t)type * ASZ
                              + ((size_t)bs * Ac + a) * Dc);
        o[tid]       = make_float4(a0v.x*inv, a0v.y*inv, a0v.z*inv, a0v.w*inv);
        o[tid + 64]  = make_float4(a1v.x*inv, a1v.y*inv, a1v.z*inv, a1v.w*inv);
        o[tid + 128] = make_float4(a2v.x*inv, a2v.y*inv, a2v.z*inv, a2v.w*inv);
    }
}

extern "C" void kernel_launch(void* const* d_in, const int* in_sizes, int n_in,
                              void* d_out, int out_size)
{
    const float* emb   = (const float*)d_in[0];  // [B,S,L,D] f32
    const int*   masks = (const int*)d_in[1];    // [B,S,L] i32
    const int*   sids  = (const int*)d_in[2];    // [B,S,L] i32
    const int*   pred  = (const int*)d_in[3];    // [B,S,A,T] i32
    const int*   a0    = (const int*)d_in[4];    // [B,S,A,T] i32
    const int*   a1    = (const int*)d_in[5];    // [B,S,A,T] i32
    float*       out   = (float*)d_out;

    // zero the mean-pool region (atomic accumulation target)
    srl_zero_kernel<<<(Bc * Sc * Dc) / (256 * 4), 256>>>(out);

    // fused: 6 mean-pool blocks + 1 slot block per (b,s)
    srl_main_kernel<<<Bc * Sc * RPB, NTHR>>>(emb, masks, sids, pred, a0, a1, out);
}

// round 11
// speedup vs baseline: 1.2165x; 1.2165x over previous
#include <cuda_runtime.h>
#include <cstdint>

// Problem constants
#define Bc 16
#define Sc 24
#define Lc 128
#define Dc 768
#define Ac 8
#define Tc 8
#define NSLOT 24          // 3 arg types * A=8
#define NST (NSLOT * Tc)  // 192
#define MAXPAIRS (NSLOT * Lc)

// scratch for the second mean-pool half (static device global: allowed)
__device__ float g_scratch[Bc * Sc * Dc];

// ---------------- Kernel A: masked mean-pool, L-split x2 ---------------------
// grid (B*S, 3, 2); 64 threads; thread owns 1 float4 column; CTA does 64 rows.
__global__ __launch_bounds__(64)
void srl_meanpool_kernel(const float* __restrict__ emb,
                         const int* __restrict__ masks,
                         float* __restrict__ out)
{
    __shared__ float s_maskf[Lc];
    __shared__ float s_wcnt[2];

    const int bs  = blockIdx.x;
    const int cy  = blockIdx.y;     // column third
    const int lh  = blockIdx.z;     // L half
    const int tid = threadIdx.x;

    // stage full mask + total count (count over FULL L)
    float m0 = (float)masks[bs * Lc + tid];
    float m1 = (float)masks[bs * Lc + tid + 64];
    s_maskf[tid]      = m0;
    s_maskf[tid + 64] = m1;
    {
        float c = m0 + m1;
        #pragma unroll
        for (int off = 16; off; off >>= 1)
            c += __shfl_xor_sync(0xffffffffu, c, off);
        if ((tid & 31) == 0) s_wcnt[tid >> 5] = c;
    }
    __syncthreads();
    const float inv = 1.0f / fmaxf(s_wcnt[0] + s_wcnt[1], 1.0f);

    const int colv  = cy * 64 + tid;               // float4 column (0..191)
    const int lbase = lh * 64;
    const float4* ep = (const float4*)(emb + (size_t)bs * Lc * Dc) + colv;

    float4 acc = make_float4(0.f, 0.f, 0.f, 0.f);

    #pragma unroll 1
    for (int lb = 0; lb < 64; lb += 8) {
        float4 v[8];
        #pragma unroll
        for (int i = 0; i < 8; i++)
            v[i] = ep[(size_t)(lbase + lb + i) * (Dc / 4)];
        #pragma unroll
        for (int i = 0; i < 8; i++) {
            float mf = s_maskf[lbase + lb + i];
            acc.x = fmaf(v[i].x, mf, acc.x);
            acc.y = fmaf(v[i].y, mf, acc.y);
            acc.z = fmaf(v[i].z, mf, acc.z);
            acc.w = fmaf(v[i].w, mf, acc.w);
        }
    }

    float* dstBase = (lh == 0) ? out : g_scratch;
    float4* o = (float4*)(dstBase + (size_t)bs * Dc) + colv;
    *o = make_float4(acc.x * inv, acc.y * inv, acc.z * inv, acc.w * inv);
}

// ---------------- Kernel B: combine halves + slot gather ---------------------
// grid (B*S); 192 threads; thread owns 1 float4 column of the 768-col row.
#define B_NTHR 192

__global__ __launch_bounds__(B_NTHR)
void srl_slot_kernel(const float* __restrict__ emb,
                     const int* __restrict__ sids,
                     const int* __restrict__ pred_ids,
                     const int* __restrict__ arg0_ids,
                     const int* __restrict__ arg1_ids,
                     float* __restrict__ out)
{
    __shared__ int            s_sid[Lc];
    __shared__ int            s_argids[NST];
    __shared__ int            s_cnt[NST];
    __shared__ int            s_chosen[NSLOT];
    __shared__ float          s_invc[NSLOT];
    __shared__ int            s_nm[NSLOT];
    __shared__ int            s_off[NSLOT + 1];
    __shared__ unsigned int   s_bm[NSLOT][4];       // ballot masks per warp
    __shared__ unsigned short s_pairs[MAXPAIRS];    // (slot<<8)|l, slot-major

    const int bs   = blockIdx.x;
    const int tid  = threadIdx.x;
    const int lane = tid & 31;
    const int wid  = tid >> 5;

    const size_t OFF0 = (size_t)Bc * Sc * Dc;
    const size_t ASZ  = (size_t)Bc * Sc * Ac * Dc;

    // ---- combine the two mean-pool halves (deterministic order: out + scratch)
    {
        float4* o = (float4*)(out + (size_t)bs * Dc) + tid;
        const float4* p = (const float4*)(g_scratch + (size_t)bs * Dc) + tid;
        float4 a = *o, b = *p;
        *o = make_float4(a.x + b.x, a.y + b.y, a.z + b.z, a.w + b.w);
    }

    // ---- stage metadata
    if (tid < Lc) s_sid[tid] = sids[bs * Lc + tid];
    {
        int slot = tid / Tc, t = tid % Tc;
        int type = slot / Ac, a = slot % Ac;
        const int* src = (type == 0) ? pred_ids : (type == 1) ? arg0_ids : arg1_ids;
        s_argids[tid] = src[(bs * Ac + a) * Tc + t];
    }
    __syncthreads();

    // ---- per-(slot,t) match counts (192 parallel threads)
    {
        int id = s_argids[tid];
        int c = 0;
        if (id != 0) {
            #pragma unroll 8
            for (int l = 0; l < Lc; l++) c += (s_sid[l] == id);
        }
        s_cnt[tid] = c;
    }
    __syncthreads();

    // ---- per-slot chosen id / count
    if (tid < NSLOT) {
        int chosen = -1, nm = 0;
        float invc = 1.0f;
        #pragma unroll
        for (int t = Tc - 1; t >= 0; t--) {
            int c = s_cnt[tid * Tc + t];
            if (c > 0) { chosen = s_argids[tid * Tc + t]; nm = c;
                         invc = 1.0f / (float)c; break; }
        }
        s_chosen[tid] = chosen;
        s_invc[tid]   = invc;
        s_nm[tid]     = nm;
    }
    __syncthreads();

    // ---- parallel ballot: which l positions match each slot's chosen id
    if (wid < 4) {               // warps 0..3 cover l = 0..127
        int sid = s_sid[tid];
        #pragma unroll
        for (int s = 0; s < NSLOT; s++) {
            unsigned int bm = __ballot_sync(0xffffffffu, sid == s_chosen[s]);
            if (lane == 0) s_bm[s][wid] = bm;
        }
    }
    if (tid == 0) {
        int o = 0;
        #pragma unroll
        for (int s = 0; s < NSLOT; s++) { s_off[s] = o; o += s_nm[s]; }
        s_off[NSLOT] = o;
    }
    __syncthreads();

    // ---- parallel pair-list build: rank via popc (slot-major, l-ordered)
    if (wid < 4) {
        int sid = s_sid[tid];
        const unsigned int ltmask = (lane == 31) ? 0x7fffffffu
                                                 : ((1u << lane) - 1u);
        #pragma unroll 4
        for (int s = 0; s < NSLOT; s++) {
            if (sid == s_chosen[s]) {
                int rank = __popc(s_bm[s][wid] & ltmask);
                #pragma unroll
                for (int w = 0; w < 4; w++)
                    if (w < wid) rank += __popc(s_bm[s][w]);
                s_pairs[s_off[s] + rank] = (unsigned short)((s << 8) | tid);
            }
        }
    }
    __syncthreads();

    const int npairs = s_off[NSLOT];

    // ---- zero outputs for empty slots
    #pragma unroll
    for (int s = 0; s < NSLOT; s++) {
        if (s_nm[s] == 0) {
            int type = s / Ac, a = s % Ac;
            float4* o = (float4*)(out + OFF0 + (size_t)type * ASZ
                                  + ((size_t)bs * Ac + a) * Dc) + tid;
            *o = make_float4(0.f, 0.f, 0.f, 0.f);
        }
    }

    // ---- batched gather: 8 rows in flight (1 float4/thread/row), flush on
    //      slot change (slot-major ordering keeps each slot contiguous)
    const float4* ebase = (const float4*)(emb + (size_t)bs * Lc * Dc) + tid;
    float4 acc = make_float4(0.f, 0.f, 0.f, 0.f);
    int cur = -1;

    for (int p0 = 0; p0 < npairs; p0 += 8) {
        const int nb = min(8, npairs - p0);
        float4 v[8];
        int    sl[8];
        #pragma unroll
        for (int i = 0; i < 8; i++) {
            if (i < nb) {
                int pr = s_pairs[p0 + i];          // uniform broadcast LDS
                sl[i] = pr >> 8;
                v[i]  = ebase[(size_t)(pr & 255) * (Dc / 4)];
            }
        }
        #pragma unroll
        for (int i = 0; i < 8; i++) {
            if (i < nb) {
                if (sl[i] != cur) {
                    if (cur >= 0) {
                        float inv = s_invc[cur];
                        int type = cur / Ac, a = cur % Ac;
                        float4* o = (float4*)(out + OFF0 + (size_t)type * ASZ
                                              + ((size_t)bs * Ac + a) * Dc) + tid;
                        *o = make_float4(acc.x * inv, acc.y * inv,
                                         acc.z * inv, acc.w * inv);
                    }
                    cur = sl[i];
                    acc = v[i];
                } else {
                    acc.x += v[i].x; acc.y += v[i].y;
                    acc.z += v[i].z; acc.w += v[i].w;
                }
            }
        }
    }
    if (cur >= 0) {
        float inv = s_invc[cur];
        int type = cur / Ac, a = cur % Ac;
        float4* o = (float4*)(out + OFF0 + (size_t)type * ASZ
                              + ((size_t)bs * Ac + a) * Dc) + tid;
        *o = make_float4(acc.x * inv, acc.y * inv, acc.z * inv, acc.w * inv);
    }
}

extern "C" void kernel_launch(void* const* d_in, const int* in_sizes, int n_in,
                              void* d_out, int out_size)
{
    const float* emb   = (const float*)d_in[0];  // [B,S,L,D] f32
    const int*   masks = (const int*)d_in[1];    // [B,S,L] i32
    const int*   sids  = (const int*)d_in[2];    // [B,S,L] i32
    const int*   pred  = (const int*)d_in[3];    // [B,S,A,T] i32
    const int*   a0    = (const int*)d_in[4];    // [B,S,A,T] i32
    const int*   a1    = (const int*)d_in[5];    // [B,S,A,T] i32
    float*       out   = (float*)d_out;

    dim3 gridA(Bc * Sc, 3, 2);
    srl_meanpool_kernel<<<gridA, 64>>>(emb, masks, out);

    srl_slot_kernel<<<Bc * Sc, B_NTHR>>>(emb, sids, pred, a0, a1, out);
}

// round 13
// speedup vs baseline: 1.3181x; 1.0836x over previous
#include <cuda_runtime.h>
#include <cstdint>

// Problem constants
#define Bc 16
#define Sc 24
#define Lc 128
#define Dc 768
#define Ac 8
#define Tc 8
#define NSLOT 24            // 3 arg types * A=8
#define SLOTS_PER_TYPE 8
#define MAXPAIRS_T (SLOTS_PER_TYPE * Lc)   // 1024 per-type worst case

#define LSPLIT 4            // mean-pool L split
#define LROWS (Lc / LSPLIT) // 32 rows per CTA

// scratch for mean-pool partials lh=1..3 (static device global: allowed)
__device__ float g_scratch[3][Bc * Sc * Dc];

// ---------------- Kernel A: masked mean-pool, L-split x4 ---------------------
// grid (B*S, 3, 4); 64 threads; thread owns 1 float4 column; CTA does 32 rows.
__global__ __launch_bounds__(64)
void srl_meanpool_kernel(const float* __restrict__ emb,
                         const int* __restrict__ masks,
                         float* __restrict__ out)
{
    __shared__ float s_maskf[Lc];
    __shared__ float s_wcnt[2];

    const int bs  = blockIdx.x;
    const int cy  = blockIdx.y;     // column third
    const int lh  = blockIdx.z;     // L quarter
    const int tid = threadIdx.x;

    // stage full mask + total count (count over FULL L)
    float m0 = (float)masks[bs * Lc + tid];
    float m1 = (float)masks[bs * Lc + tid + 64];
    s_maskf[tid]      = m0;
    s_maskf[tid + 64] = m1;
    {
        float c = m0 + m1;
        #pragma unroll
        for (int off = 16; off; off >>= 1)
            c += __shfl_xor_sync(0xffffffffu, c, off);
        if ((tid & 31) == 0) s_wcnt[tid >> 5] = c;
    }
    __syncthreads();
    const float inv = 1.0f / fmaxf(s_wcnt[0] + s_wcnt[1], 1.0f);

    const int colv  = cy * 64 + tid;               // float4 column (0..191)
    const int lbase = lh * LROWS;
    const float4* ep = (const float4*)(emb + (size_t)bs * Lc * Dc) + colv;

    float4 acc = make_float4(0.f, 0.f, 0.f, 0.f);

    #pragma unroll 1
    for (int lb = 0; lb < LROWS; lb += 8) {
        float4 v[8];
        #pragma unroll
        for (int i = 0; i < 8; i++)
            v[i] = ep[(size_t)(lbase + lb + i) * (Dc / 4)];
        #pragma unroll
        for (int i = 0; i < 8; i++) {
            float mf = s_maskf[lbase + lb + i];
            acc.x = fmaf(v[i].x, mf, acc.x);
            acc.y = fmaf(v[i].y, mf, acc.y);
            acc.z = fmaf(v[i].z, mf, acc.z);
            acc.w = fmaf(v[i].w, mf, acc.w);
        }
    }

    float* dstBase = (lh == 0) ? out : &g_scratch[lh - 1][0];
    float4* o = (float4*)(dstBase + (size_t)bs * Dc) + colv;
    *o = make_float4(acc.x * inv, acc.y * inv, acc.z * inv, acc.w * inv);
}

// ---------------- Kernel B: per-(bs,type) slot gather + mean combine ---------
// grid (B*S*3); 192 threads; thread owns 1 float4 column of the 768-col row.
#define B_NTHR 192

__global__ __launch_bounds__(B_NTHR)
void srl_slot_kernel(const float* __restrict__ emb,
                     const int* __restrict__ sids,
                     const int* __restrict__ pred_ids,
                     const int* __restrict__ arg0_ids,
                     const int* __restrict__ arg1_ids,
                     float* __restrict__ out)
{
    __shared__ int            s_sid[Lc];
    __shared__ int            s_argids[SLOTS_PER_TYPE * Tc];   // 64
    __shared__ int            s_cnt[SLOTS_PER_TYPE * Tc];
    __shared__ int            s_chosen[SLOTS_PER_TYPE];
    __shared__ float          s_invc[SLOTS_PER_TYPE];
    __shared__ int            s_nm[SLOTS_PER_TYPE];
    __shared__ int            s_off[SLOTS_PER_TYPE + 1];
    __shared__ unsigned int   s_bm[SLOTS_PER_TYPE][4];
    __shared__ unsigned short s_pairs[MAXPAIRS_T];  // (slot<<8)|l, slot-major

    const int blk  = blockIdx.x;        // 0 .. B*S*3-1
    const int bs   = blk / 3;
    const int type = blk % 3;
    const int tid  = threadIdx.x;
    const int lane = tid & 31;
    const int wid  = tid >> 5;

    const size_t OFF0 = (size_t)Bc * Sc * Dc;
    const size_t ASZ  = (size_t)Bc * Sc * Ac * Dc;

    // ---- type-0 CTA also combines the 4 mean-pool partials (fixed order)
    if (type == 0) {
        float4* o  = (float4*)(out + (size_t)bs * Dc) + tid;
        const float4* p0 = (const float4*)(&g_scratch[0][0] + (size_t)bs * Dc) + tid;
        const float4* p1 = (const float4*)(&g_scratch[1][0] + (size_t)bs * Dc) + tid;
        const float4* p2 = (const float4*)(&g_scratch[2][0] + (size_t)bs * Dc) + tid;
        float4 a = *o, b = *p0, c = *p1, d = *p2;
        a.x = ((a.x + b.x) + c.x) + d.x;
        a.y = ((a.y + b.y) + c.y) + d.y;
        a.z = ((a.z + b.z) + c.z) + d.z;
        a.w = ((a.w + b.w) + c.w) + d.w;
        *o = a;
    }

    // ---- stage metadata
    if (tid < Lc) s_sid[tid] = sids[bs * Lc + tid];
    const int* src = (type == 0) ? pred_ids : (type == 1) ? arg0_ids : arg1_ids;
    if (tid < SLOTS_PER_TYPE * Tc) {
        int a = tid / Tc, t = tid % Tc;
        s_argids[tid] = src[(bs * Ac + a) * Tc + t];
    }
    __syncthreads();

    // ---- per-(slot,t) match counts (64 threads scan LDS)
    if (tid < SLOTS_PER_TYPE * Tc) {
        int id = s_argids[tid];
        int c = 0;
        if (id != 0) {
            #pragma unroll 8
            for (int l = 0; l < Lc; l++) c += (s_sid[l] == id);
        }
        s_cnt[tid] = c;
    }
    __syncthreads();

    // ---- per-slot chosen id / count
    if (tid < SLOTS_PER_TYPE) {
        int chosen = -1, nm = 0;
        float invc = 1.0f;
        #pragma unroll
        for (int t = Tc - 1; t >= 0; t--) {
            int c = s_cnt[tid * Tc + t];
            if (c > 0) { chosen = s_argids[tid * Tc + t]; nm = c;
                         invc = 1.0f / (float)c; break; }
        }
        s_chosen[tid] = chosen;
        s_invc[tid]   = invc;
        s_nm[tid]     = nm;
    }
    __syncthreads();

    // ---- parallel ballot: which l positions match each slot's chosen id
    if (wid < 4) {               // warps 0..3 cover l = 0..127
        int sid = s_sid[tid];
        #pragma unroll
        for (int s = 0; s < SLOTS_PER_TYPE; s++) {
            unsigned int bm = __ballot_sync(0xffffffffu, sid == s_chosen[s]);
            if (lane == 0) s_bm[s][wid] = bm;
        }
    }
    if (tid == 0) {
        int o = 0;
        #pragma unroll
        for (int s = 0; s < SLOTS_PER_TYPE; s++) { s_off[s] = o; o += s_nm[s]; }
        s_off[SLOTS_PER_TYPE] = o;
    }
    __syncthreads();

    // ---- parallel pair-list build: rank via popc (slot-major, l-ordered)
    if (wid < 4) {
        int sid = s_sid[tid];
        const unsigned int ltmask = (lane == 31) ? 0x7fffffffu
                                                 : ((1u << lane) - 1u);
        #pragma unroll
        for (int s = 0; s < SLOTS_PER_TYPE; s++) {
            if (sid == s_chosen[s]) {
                int rank = __popc(s_bm[s][wid] & ltmask);
                #pragma unroll
                for (int w = 0; w < 4; w++)
                    if (w < wid) rank += __popc(s_bm[s][w]);
                s_pairs[s_off[s] + rank] = (unsigned short)((s << 8) | tid);
            }
        }
    }
    __syncthreads();

    const int npairs = s_off[SLOTS_PER_TYPE];

    // ---- zero outputs for empty slots
    #pragma unroll
    for (int s = 0; s < SLOTS_PER_TYPE; s++) {
        if (s_nm[s] == 0) {
            float4* o = (float4*)(out + OFF0 + (size_t)type * ASZ
                                  + ((size_t)bs * Ac + s) * Dc) + tid;
            *o = make_float4(0.f, 0.f, 0.f, 0.f);
        }
    }

    // ---- batched gather: 8 rows in flight (1 float4/thread/row), flush on
    //      slot change (slot-major ordering keeps each slot contiguous)
    const float4* ebase = (const float4*)(emb + (size_t)bs * Lc * Dc) + tid;
    float4 acc = make_float4(0.f, 0.f, 0.f, 0.f);
    int cur = -1;

    for (int p0 = 0; p0 < npairs; p0 += 8) {
        const int nb = min(8, npairs - p0);
        float4 v[8];
        int    sl[8];
        #pragma unroll
        for (int i = 0; i < 8; i++) {
            if (i < nb) {
                int pr = s_pairs[p0 + i];          // uniform broadcast LDS
                sl[i] = pr >> 8;
                v[i]  = ebase[(size_t)(pr & 255) * (Dc / 4)];
            }
        }
        #pragma unroll
        for (int i = 0; i < 8; i++) {
            if (i < nb) {
                if (sl[i] != cur) {
                    if (cur >= 0) {
                        float inv = s_invc[cur];
                        float4* o = (float4*)(out + OFF0 + (size_t)type * ASZ
                                              + ((size_t)bs * Ac + cur) * Dc) + tid;
                        *o = make_float4(acc.x * inv, acc.y * inv,
                                         acc.z * inv, acc.w * inv);
                    }
                    cur = sl[i];
                    acc = v[i];
                } else {
                    acc.x += v[i].x; acc.y += v[i].y;
                    acc.z += v[i].z; acc.w += v[i].w;
                }
            }
        }
    }
    if (cur >= 0) {
        float inv = s_invc[cur];
        float4* o = (float4*)(out + OFF0 + (size_t)type * ASZ
                              + ((size_t)bs * Ac + cur) * Dc) + tid;
        *o = make_float4(acc.x * inv, acc.y * inv, acc.z * inv, acc.w * inv);
    }
}

extern "C" void kernel_launch(void* const* d_in, const int* in_sizes, int n_in,
                              void* d_out, int out_size)
{
    const float* emb   = (const float*)d_in[0];  // [B,S,L,D] f32
    const int*   masks = (const int*)d_in[1];    // [B,S,L] i32
    const int*   sids  = (const int*)d_in[2];    // [B,S,L] i32
    const int*   pred  = (const int*)d_in[3];    // [B,S,A,T] i32
    const int*   a0    = (const int*)d_in[4];    // [B,S,A,T] i32
    const int*   a1    = (const int*)d_in[5];    // [B,S,A,T] i32
    float*       out   = (float*)d_out;

    dim3 gridA(Bc * Sc, 3, LSPLIT);
    srl_meanpool_kernel<<<gridA, 64>>>(emb, masks, out);

    srl_slot_kernel<<<Bc * Sc * 3, B_NTHR>>>(emb, sids, pred, a0, a1, out);
}

// round 14
// speedup vs baseline: 1.4394x; 1.0920x over previous
#include <cuda_runtime.h>
#include <cstdint>

// Problem constants
#define Bc 16
#define Sc 24
#define Lc 128
#define Dc 768
#define Ac 8
#define Tc 8
#define SLOTS_PER_TYPE 8
#define MAXPAIRS_T (SLOTS_PER_TYPE * Lc)

#define LSPLIT 4
#define LROWS (Lc / LSPLIT)     // 32 rows per A-block
#define NTHR 192                // Dc/4 = 192 float4 columns
#define NBLK_B (Bc * Sc * 3)    // 1152
#define NBLK_A (Bc * Sc * LSPLIT) // 1536

// mean-pool partials, pre-scaled by 1/count (static device global: allowed)
__device__ float g_scratch[LSPLIT][Bc * Sc * Dc];

// ---------------- Fused kernel: B-blocks (slot gather) then A-blocks --------
__global__ __launch_bounds__(NTHR)
void srl_fused_kernel(const float* __restrict__ emb,
                      const int* __restrict__ masks,
                      const int* __restrict__ sids,
                      const int* __restrict__ pred_ids,
                      const int* __restrict__ arg0_ids,
                      const int* __restrict__ arg1_ids,
                      float* __restrict__ out)
{
    const int bid = blockIdx.x;
    const int tid = threadIdx.x;

    if (bid >= NBLK_B) {
        // ===================== A-block: mean-pool partial ====================
        __shared__ float s_maskf[Lc];
        __shared__ float s_wcnt[4];

        const int aidx = bid - NBLK_B;
        const int bs   = aidx % (Bc * Sc);
        const int lh   = aidx / (Bc * Sc);
        const int lane = tid & 31;
        const int wid  = tid >> 5;

        // stage full mask + total count over FULL L
        if (tid < Lc) {
            float m = (float)masks[bs * Lc + tid];
            s_maskf[tid] = m;
            float c = m;
            #pragma unroll
            for (int off = 16; off; off >>= 1)
                c += __shfl_xor_sync(0xffffffffu, c, off);
            if (lane == 0) s_wcnt[wid] = c;
        }
        __syncthreads();
        const float inv = 1.0f / fmaxf(s_wcnt[0] + s_wcnt[1] +
                                       s_wcnt[2] + s_wcnt[3], 1.0f);

        const int lbase = lh * LROWS;
        const float4* ep = (const float4*)(emb + (size_t)bs * Lc * Dc) + tid;

        float4 acc = make_float4(0.f, 0.f, 0.f, 0.f);

        #pragma unroll 1
        for (int lb = 0; lb < LROWS; lb += 8) {
            float4 v[8];
            #pragma unroll
            for (int i = 0; i < 8; i++)
                v[i] = ep[(size_t)(lbase + lb + i) * (Dc / 4)];
            #pragma unroll
            for (int i = 0; i < 8; i++) {
                float mf = s_maskf[lbase + lb + i];
                acc.x = fmaf(v[i].x, mf, acc.x);
                acc.y = fmaf(v[i].y, mf, acc.y);
                acc.z = fmaf(v[i].z, mf, acc.z);
                acc.w = fmaf(v[i].w, mf, acc.w);
            }
        }

        float4* o = (float4*)(&g_scratch[lh][0] + (size_t)bs * Dc) + tid;
        *o = make_float4(acc.x * inv, acc.y * inv, acc.z * inv, acc.w * inv);
        return;
    }

    // ======================= B-block: slot gather ============================
    __shared__ int            s_sid[Lc];
    __shared__ int            s_argids[SLOTS_PER_TYPE * Tc];
    __shared__ int            s_cnt[SLOTS_PER_TYPE * Tc];
    __shared__ int            s_chosen[SLOTS_PER_TYPE];
    __shared__ float          s_invc[SLOTS_PER_TYPE];
    __shared__ int            s_nm[SLOTS_PER_TYPE];
    __shared__ int            s_off[SLOTS_PER_TYPE + 1];
    __shared__ unsigned int   s_bm[SLOTS_PER_TYPE][4];
    __shared__ unsigned short s_pairs[MAXPAIRS_T];

    const int bs   = bid / 3;
    const int type = bid % 3;
    const int lane = tid & 31;
    const int wid  = tid >> 5;

    const size_t OFF0 = (size_t)Bc * Sc * Dc;
    const size_t ASZ  = (size_t)Bc * Sc * Ac * Dc;

    // stage metadata
    if (tid < Lc) s_sid[tid] = sids[bs * Lc + tid];
    const int* src = (type == 0) ? pred_ids : (type == 1) ? arg0_ids : arg1_ids;
    if (tid < SLOTS_PER_TYPE * Tc) {
        int a = tid / Tc, t = tid % Tc;
        s_argids[tid] = src[(bs * Ac + a) * Tc + t];
    }
    __syncthreads();

    // per-(slot,t) match counts
    if (tid < SLOTS_PER_TYPE * Tc) {
        int id = s_argids[tid];
        int c = 0;
        if (id != 0) {
            #pragma unroll 8
            for (int l = 0; l < Lc; l++) c += (s_sid[l] == id);
        }
        s_cnt[tid] = c;
    }
    __syncthreads();

    // per-slot chosen id / count
    if (tid < SLOTS_PER_TYPE) {
        int chosen = -1, nm = 0;
        float invc = 1.0f;
        #pragma unroll
        for (int t = Tc - 1; t >= 0; t--) {
            int c = s_cnt[tid * Tc + t];
            if (c > 0) { chosen = s_argids[tid * Tc + t]; nm = c;
                         invc = 1.0f / (float)c; break; }
        }
        s_chosen[tid] = chosen;
        s_invc[tid]   = invc;
        s_nm[tid]     = nm;
    }
    __syncthreads();

    // parallel ballot: which l positions match each slot's chosen id
    if (wid < 4) {
        int sid = s_sid[tid];
        #pragma unroll
        for (int s = 0; s < SLOTS_PER_TYPE; s++) {
            unsigned int bm = __ballot_sync(0xffffffffu, sid == s_chosen[s]);
            if (lane == 0) s_bm[s][wid] = bm;
        }
    }
    if (tid == 0) {
        int o = 0;
        #pragma unroll
        for (int s = 0; s < SLOTS_PER_TYPE; s++) { s_off[s] = o; o += s_nm[s]; }
        s_off[SLOTS_PER_TYPE] = o;
    }
    __syncthreads();

    // parallel pair-list build (slot-major, l-ordered => deterministic)
    if (wid < 4) {
        int sid = s_sid[tid];
        const unsigned int ltmask = (lane == 31) ? 0x7fffffffu
                                                 : ((1u << lane) - 1u);
        #pragma unroll
        for (int s = 0; s < SLOTS_PER_TYPE; s++) {
            if (sid == s_chosen[s]) {
                int rank = __popc(s_bm[s][wid] & ltmask);
                #pragma unroll
                for (int w = 0; w < 4; w++)
                    if (w < wid) rank += __popc(s_bm[s][w]);
                s_pairs[s_off[s] + rank] = (unsigned short)((s << 8) | tid);
            }
        }
    }
    __syncthreads();

    const int npairs = s_off[SLOTS_PER_TYPE];

    // zero outputs for empty slots
    #pragma unroll
    for (int s = 0; s < SLOTS_PER_TYPE; s++) {
        if (s_nm[s] == 0) {
            float4* o = (float4*)(out + OFF0 + (size_t)type * ASZ
                                  + ((size_t)bs * Ac + s) * Dc) + tid;
            *o = make_float4(0.f, 0.f, 0.f, 0.f);
        }
    }

    // batched gather: 8 rows in flight, flush on slot change
    const float4* ebase = (const float4*)(emb + (size_t)bs * Lc * Dc) + tid;
    float4 acc = make_float4(0.f, 0.f, 0.f, 0.f);
    int cur = -1;

    for (int p0 = 0; p0 < npairs; p0 += 8) {
        const int nb = min(8, npairs - p0);
        float4 v[8];
        int    sl[8];
        #pragma unroll
        for (int i = 0; i < 8; i++) {
            if (i < nb) {
                int pr = s_pairs[p0 + i];
                sl[i] = pr >> 8;
                v[i]  = ebase[(size_t)(pr & 255) * (Dc / 4)];
            }
        }
        #pragma unroll
        for (int i = 0; i < 8; i++) {
            if (i < nb) {
                if (sl[i] != cur) {
                    if (cur >= 0) {
                        float inv = s_invc[cur];
                        float4* o = (float4*)(out + OFF0 + (size_t)type * ASZ
                                              + ((size_t)bs * Ac + cur) * Dc) + tid;
                        *o = make_float4(acc.x * inv, acc.y * inv,
                                         acc.z * inv, acc.w * inv);
                    }
                    cur = sl[i];
                    acc = v[i];
                } else {
                    acc.x += v[i].x; acc.y += v[i].y;
                    acc.z += v[i].z; acc.w += v[i].w;
                }
            }
        }
    }
    if (cur >= 0) {
        float inv = s_invc[cur];
        float4* o = (float4*)(out + OFF0 + (size_t)type * ASZ
                              + ((size_t)bs * Ac + cur) * Dc) + tid;
        *o = make_float4(acc.x * inv, acc.y * inv, acc.z * inv, acc.w * inv);
    }
}

// ---------------- Combine kernel: sum the 4 mean-pool partials ---------------
__global__ __launch_bounds__(NTHR)
void srl_combine_kernel(float* __restrict__ out)
{
    const int bs  = blockIdx.x;
    const int tid = threadIdx.x;

    const float4* p0 = (const float4*)(&g_scratch[0][0] + (size_t)bs * Dc) + tid;
    const float4* p1 = (const float4*)(&g_scratch[1][0] + (size_t)bs * Dc) + tid;
    const float4* p2 = (const float4*)(&g_scratch[2][0] + (size_t)bs * Dc) + tid;
    const float4* p3 = (const float4*)(&g_scratch[3][0] + (size_t)bs * Dc) + tid;

    float4 a = *p0, b = *p1, c = *p2, d = *p3;
    a.x = ((a.x + b.x) + c.x) + d.x;
    a.y = ((a.y + b.y) + c.y) + d.y;
    a.z = ((a.z + b.z) + c.z) + d.z;
    a.w = ((a.w + b.w) + c.w) + d.w;

    float4* o = (float4*)(out + (size_t)bs * Dc) + tid;
    *o = a;
}

extern "C" void kernel_launch(void* const* d_in, const int* in_sizes, int n_in,
                              void* d_out, int out_size)
{
    const float* emb   = (const float*)d_in[0];  // [B,S,L,D] f32
    const int*   masks = (const int*)d_in[1];    // [B,S,L] i32
    const int*   sids  = (const int*)d_in[2];    // [B,S,L] i32
    const int*   pred  = (const int*)d_in[3];    // [B,S,A,T] i32
    const int*   a0    = (const int*)d_in[4];    // [B,S,A,T] i32
    const int*   a1    = (const int*)d_in[5];    // [B,S,A,T] i32
    float*       out   = (float*)d_out;

    srl_fused_kernel<<<NBLK_B + NBLK_A, NTHR>>>(emb, masks, sids,
                                                pred, a0, a1, out);
    srl_combine_kernel<<<Bc * Sc, NTHR>>>(out);
}

// round 16
// speedup vs baseline: 1.6251x; 1.1290x over previous
#include <cuda_runtime.h>
#include <cstdint>

// Problem constants
#define Bc 16
#define Sc 24
#define Lc 128
#define Dc 768
#define Ac 8
#define Tc 8
#define SLOTS_PER_TYPE 8
#define MAXPAIRS_T (SLOTS_PER_TYPE * Lc)

#define LSPLIT 4
#define LROWS (Lc / LSPLIT)       // 32 rows per A-block
#define NTHR 192                  // Dc/4 float4 columns
#define GRP 7                     // 3 B-blocks + 4 A-blocks per bs
#define NBLK (Bc * Sc * GRP)      // 2688

// mean-pool partials, pre-scaled by 1/count (static device global: allowed)
__device__ float        g_scratch[LSPLIT][Bc * Sc * Dc];
// arrival counter per bs; never reset — modulo-LSPLIT selects last arriver.
__device__ unsigned int g_counter[Bc * Sc];

__global__ __launch_bounds__(NTHR)
void srl_fused_kernel(const float* __restrict__ emb,
                      const int* __restrict__ masks,
                      const int* __restrict__ sids,
                      const int* __restrict__ pred_ids,
                      const int* __restrict__ arg0_ids,
                      const int* __restrict__ arg1_ids,
                      float* __restrict__ out)
{
    const int bid = blockIdx.x;
    const int tid = threadIdx.x;
    const int g   = bid / GRP;     // bs
    const int r   = bid % GRP;     // 0..2: B-block (type r); 3..6: A-block (lh r-3)

    if (r >= 3) {
        // ===================== A-block: mean-pool partial ====================
        __shared__ float s_maskf[Lc];
        __shared__ float s_wcnt[4];
        __shared__ int   s_last;

        const int bs   = g;
        const int lh   = r - 3;
        const int lane = tid & 31;
        const int wid  = tid >> 5;

        if (tid < Lc) {
            float m = (float)masks[bs * Lc + tid];
            s_maskf[tid] = m;
            float c = m;
            #pragma unroll
            for (int off = 16; off; off >>= 1)
                c += __shfl_xor_sync(0xffffffffu, c, off);
            if (lane == 0) s_wcnt[wid] = c;
        }
        __syncthreads();
        const float inv = 1.0f / fmaxf(s_wcnt[0] + s_wcnt[1] +
                                       s_wcnt[2] + s_wcnt[3], 1.0f);

        const int lbase = lh * LROWS;
        const float4* ep = (const float4*)(emb + (size_t)bs * Lc * Dc) + tid;

        float4 acc = make_float4(0.f, 0.f, 0.f, 0.f);

        #pragma unroll 1
        for (int lb = 0; lb < LROWS; lb += 8) {
            float4 v[8];
            #pragma unroll
            for (int i = 0; i < 8; i++)
                v[i] = ep[(size_t)(lbase + lb + i) * (Dc / 4)];
            #pragma unroll
            for (int i = 0; i < 8; i++) {
                float mf = s_maskf[lbase + lb + i];
                acc.x = fmaf(v[i].x, mf, acc.x);
                acc.y = fmaf(v[i].y, mf, acc.y);
                acc.z = fmaf(v[i].z, mf, acc.z);
                acc.w = fmaf(v[i].w, mf, acc.w);
            }
        }

        float4* o = (float4*)(&g_scratch[lh][0] + (size_t)bs * Dc) + tid;
        *o = make_float4(acc.x * inv, acc.y * inv, acc.z * inv, acc.w * inv);

        // ---- last-arriving A-block for this bs combines the 4 partials
        __threadfence();
        __syncthreads();
        if (tid == 0) {
            unsigned int old = atomicAdd(&g_counter[bs], 1u);
            s_last = ((old & (LSPLIT - 1)) == (LSPLIT - 1));
        }
        __syncthreads();
        if (s_last) {
            __threadfence();   // acquire: see all partials
            const float4* p0 = (const float4*)(&g_scratch[0][0] + (size_t)bs * Dc) + tid;
            const float4* p1 = (const float4*)(&g_scratch[1][0] + (size_t)bs * Dc) + tid;
            const float4* p2 = (const float4*)(&g_scratch[2][0] + (size_t)bs * Dc) + tid;
            const float4* p3 = (const float4*)(&g_scratch[3][0] + (size_t)bs * Dc) + tid;
            float4 a = *p0, b = *p1, c = *p2, d = *p3;
            a.x = ((a.x + b.x) + c.x) + d.x;
            a.y = ((a.y + b.y) + c.y) + d.y;
            a.z = ((a.z + b.z) + c.z) + d.z;
            a.w = ((a.w + b.w) + c.w) + d.w;
            float4* oo = (float4*)(out + (size_t)bs * Dc) + tid;
            *oo = a;
        }
        return;
    }

    // ======================= B-block: slot gather ============================
    __shared__ int            s_sid[Lc];
    __shared__ int            s_argids[SLOTS_PER_TYPE * Tc];
    __shared__ int            s_cnt[SLOTS_PER_TYPE * Tc];
    __shared__ int            s_chosen[SLOTS_PER_TYPE];
    __shared__ float          s_invc[SLOTS_PER_TYPE];
    __shared__ int            s_nm[SLOTS_PER_TYPE];
    __shared__ int            s_off[SLOTS_PER_TYPE + 1];
    __shared__ unsigned int   s_bm[SLOTS_PER_TYPE][4];
    __shared__ unsigned short s_pairs[MAXPAIRS_T];

    const int bs   = g;
    const int type = r;
    const int lane = tid & 31;
    const int wid  = tid >> 5;

    const size_t OFF0 = (size_t)Bc * Sc * Dc;
    const size_t ASZ  = (size_t)Bc * Sc * Ac * Dc;

    // stage metadata
    if (tid < Lc) s_sid[tid] = sids[bs * Lc + tid];
    const int* src = (type == 0) ? pred_ids : (type == 1) ? arg0_ids : arg1_ids;
    if (tid < SLOTS_PER_TYPE * Tc) {
        int a = tid / Tc, t = tid % Tc;
        s_argids[tid] = src[(bs * Ac + a) * Tc + t];
    }
    __syncthreads();

    // per-(slot,t) match counts
    if (tid < SLOTS_PER_TYPE * Tc) {
        int id = s_argids[tid];
        int c = 0;
        if (id != 0) {
            #pragma unroll 8
            for (int l = 0; l < Lc; l++) c += (s_sid[l] == id);
        }
        s_cnt[tid] = c;
    }
    __syncthreads();

    // per-slot chosen id / count
    if (tid < SLOTS_PER_TYPE) {
        int chosen = -1, nm = 0;
        float invc = 1.0f;
        #pragma unroll
        for (int t = Tc - 1; t >= 0; t--) {
            int c = s_cnt[tid * Tc + t];
            if (c > 0) { chosen = s_argids[tid * Tc + t]; nm = c;
                         invc = 1.0f / (float)c; break; }
        }
        s_chosen[tid] = chosen;
        s_invc[tid]   = invc;
        s_nm[tid]     = nm;
    }
    __syncthreads();

    // parallel ballot: which l positions match each slot's chosen id
    if (wid < 4) {
        int sid = s_sid[tid];
        #pragma unroll
        for (int s = 0; s < SLOTS_PER_TYPE; s++) {
            unsigned int bm = __ballot_sync(0xffffffffu, sid == s_chosen[s]);
            if (lane == 0) s_bm[s][wid] = bm;
        }
    }
    if (tid == 0) {
        int o = 0;
        #pragma unroll
        for (int s = 0; s < SLOTS_PER_TYPE; s++) { s_off[s] = o; o += s_nm[s]; }
        s_off[SLOTS_PER_TYPE] = o;
    }
    __syncthreads();

    // parallel pair-list build (slot-major, l-ordered => deterministic)
    if (wid < 4) {
        int sid = s_sid[tid];
        const unsigned int ltmask = (lane == 31) ? 0x7fffffffu
                                                 : ((1u << lane) - 1u);
        #pragma unroll
        for (int s = 0; s < SLOTS_PER_TYPE; s++) {
            if (sid == s_chosen[s]) {
                int rank = __popc(s_bm[s][wid] & ltmask);
                #pragma unroll
                for (int w = 0; w < 4; w++)
                    if (w < wid) rank += __popc(s_bm[s][w]);
                s_pairs[s_off[s] + rank] = (unsigned short)((s << 8) | tid);
            }
        }
    }
    __syncthreads();

    const int npairs = s_off[SLOTS_PER_TYPE];

    // zero outputs for empty slots
    #pragma unroll
    for (int s = 0; s < SLOTS_PER_TYPE; s++) {
        if (s_nm[s] == 0) {
            float4* o = (float4*)(out + OFF0 + (size_t)type * ASZ
                                  + ((size_t)bs * Ac + s) * Dc) + tid;
            *o = make_float4(0.f, 0.f, 0.f, 0.f);
        }
    }

    // batched gather: 8 rows in flight, flush on slot change
    const float4* ebase = (const float4*)(emb + (size_t)bs * Lc * Dc) + tid;
    float4 acc = make_float4(0.f, 0.f, 0.f, 0.f);
    int cur = -1;

    for (int p0 = 0; p0 < npairs; p0 += 8) {
        const int nb = min(8, npairs - p0);
        float4 v[8];
        int    sl[8];
        #pragma unroll
        for (int i = 0; i < 8; i++) {
            if (i < nb) {
                int pr = s_pairs[p0 + i];
                sl[i] = pr >> 8;
                v[i]  = ebase[(size_t)(pr & 255) * (Dc / 4)];
            }
        }
        #pragma unroll
        for (int i = 0; i < 8; i++) {
            if (i < nb) {
                if (sl[i] != cur) {
                    if (cur >= 0) {
                        float inv = s_invc[cur];
                        float4* o = (float4*)(out + OFF0 + (size_t)type * ASZ
                                              + ((size_t)bs * Ac + cur) * Dc) + tid;
                        *o = make_float4(acc.x * inv, acc.y * inv,
                                         acc.z * inv, acc.w * inv);
                    }
                    cur = sl[i];
                    acc = v[i];
                } else {
                    acc.x += v[i].x; acc.y += v[i].y;
                    acc.z += v[i].z; acc.w += v[i].w;
                }
            }
        }
    }
    if (cur >= 0) {
        float inv = s_invc[cur];
        float4* o = (float4*)(out + OFF0 + (size_t)type * ASZ
                              + ((size_t)bs * Ac + cur) * Dc) + tid;
        *o = make_float4(acc.x * inv, acc.y * inv, acc.z * inv, acc.w * inv);
    }
}

extern "C" void kernel_launch(void* const* d_in, const int* in_sizes, int n_in,
                              void* d_out, int out_size)
{
    const float* emb   = (const float*)d_in[0];  // [B,S,L,D] f32
    const int*   masks = (const int*)d_in[1];    // [B,S,L] i32
    const int*   sids  = (const int*)d_in[2];    // [B,S,L] i32
    const int*   pred  = (const int*)d_in[3];    // [B,S,A,T] i32
    const int*   a0    = (const int*)d_in[4];    // [B,S,A,T] i32
    const int*   a1    = (const int*)d_in[5];    // [B,S,A,T] i32
    float*       out   = (float*)d_out;

    srl_fused_kernel<<<NBLK, NTHR>>>(emb, masks, sids, pred, a0, a1, out);
}